// round 2
// baseline (speedup 1.0000x reference)
#include <cuda_runtime.h>
#include <math.h>

#define BB 2
#define NN 4096
#define HH 16
#define DD 64
#define CC 1024
#define BN (BB*NN)            // 8192 tokens
#define TOK 128               // tokens per block in argmax kernel

typedef unsigned long long u64;

// Scratch (no cudaMalloc allowed): projected codebook keys/values + histogram.
__device__ __align__(16) float g_k[HH*CC*DD];   // 4 MB
__device__ __align__(16) float g_v[HH*CC*DD];   // 4 MB
__device__ int g_hist[HH*CC];

// Packed fp32x2 FMA: d = a*b + c on two independent fp32 lanes (bit-exact fp32).
__device__ __forceinline__ u64 ffma2(u64 a, u64 b, u64 c) {
    u64 d;
    asm("fma.rn.f32x2 %0, %1, %2, %3;" : "=l"(d) : "l"(a), "l"(b), "l"(c));
    return d;
}
__device__ __forceinline__ u64 fadd2(u64 a, u64 b) {
    u64 d;
    asm("add.rn.f32x2 %0, %1, %2;" : "=l"(d) : "l"(a), "l"(b));
    return d;
}
__device__ __forceinline__ u64 fmul2(u64 a, u64 b) {
    u64 d;
    asm("mul.rn.f32x2 %0, %1, %2;" : "=l"(d) : "l"(a), "l"(b));
    return d;
}
__device__ __forceinline__ void unpack2(u64 p, float& lo, float& hi) {
    asm("mov.b64 {%0, %1}, %2;" : "=f"(lo), "=f"(hi) : "l"(p));
}

// ---------------------------------------------------------------------------
// Phase A: k = codebooks @ wk, v = codebooks @ wv   (per head, 1024x64x64)
// ---------------------------------------------------------------------------
__global__ void kv_kernel(const float* __restrict__ cb,
                          const float* __restrict__ wk,
                          const float* __restrict__ wv) {
    int h  = blockIdx.x;
    int c0 = blockIdx.y * 16;
    __shared__ float s_wk[DD*DD];
    __shared__ float s_wv[DD*DD];
    __shared__ float s_cb[16*DD];
    int tid = threadIdx.x;
    for (int i = tid; i < DD*DD; i += 256) {
        s_wk[i] = wk[h*DD*DD + i];
        s_wv[i] = wv[h*DD*DD + i];
    }
    for (int i = tid; i < 16*DD; i += 256) {
        s_cb[i] = cb[(size_t)h*CC*DD + (size_t)c0*DD + i];
    }
    __syncthreads();
    int d  = tid & 63;        // output dim
    int cl = tid >> 6;        // 0..3
    for (int cc = cl; cc < 16; cc += 4) {
        float ak = 0.f, av = 0.f;
        #pragma unroll
        for (int e = 0; e < DD; e++) {
            float cbe = s_cb[cc*DD + e];
            ak = fmaf(cbe, s_wk[e*DD + d], ak);
            av = fmaf(cbe, s_wv[e*DD + d], av);
        }
        size_t off = ((size_t)h*CC + (c0 + cc))*DD + d;
        g_k[off] = ak;
        g_v[off] = av;
    }
}

__global__ void zero_hist_kernel() {
    int i = blockIdx.x * 256 + threadIdx.x;
    if (i < HH*CC) g_hist[i] = 0;
}

// ---------------------------------------------------------------------------
// Phase B: fused logits + argmax + v-gather + index write + histogram.
// One thread = one (token, head). q packed as 32 x f32x2; inner product via
// fma.rn.f32x2 (2 fp32 MACs / instr) -> 32 FFMA2 per code instead of 64 FFMA.
// ---------------------------------------------------------------------------
__global__ void __launch_bounds__(TOK)
argmax_kernel(const float* __restrict__ x, float* __restrict__ out_base) {
    int h = blockIdx.y;
    int t = blockIdx.x * TOK + threadIdx.x;      // token id in [0, BN)

    __shared__ float4 s_k[128 * 16];             // 128 codes x 64 dims

    // load q = x[t, h*64 + d] * D^-0.5, packed into 32 f32x2 regs
    u64 q2[32];
    u64 sc;
    { float2 s2 = make_float2(0.125f, 0.125f); sc = *reinterpret_cast<u64*>(&s2); }
    const ulonglong2* xq = (const ulonglong2*)(x + (size_t)t * (HH*DD) + h*DD);
    #pragma unroll
    for (int i = 0; i < 16; i++) {
        ulonglong2 p = xq[i];                    // 4 floats
        q2[2*i + 0] = fmul2(p.x, sc);
        q2[2*i + 1] = fmul2(p.y, sc);
    }

    float best = -INFINITY;
    int   bi   = 0;

    for (int jt = 0; jt < CC; jt += 128) {
        __syncthreads();
        const float4* ks = (const float4*)(g_k + ((size_t)h*CC + jt)*DD);
        for (int i = threadIdx.x; i < 128*16; i += TOK) s_k[i] = ks[i];
        __syncthreads();

        #pragma unroll 2
        for (int j = 0; j < 128; j++) {
            u64 a0 = 0ull, a1 = 0ull, a2 = 0ull, a3 = 0ull;  // packed +0.0f pairs
            const ulonglong2* kk = (const ulonglong2*)(s_k + j*16);
            #pragma unroll
            for (int i = 0; i < 16; i += 4) {
                ulonglong2 k0 = kk[i+0];
                ulonglong2 k1 = kk[i+1];
                ulonglong2 k2 = kk[i+2];
                ulonglong2 k3 = kk[i+3];
                a0 = ffma2(q2[2*i + 0], k0.x, a0);
                a1 = ffma2(q2[2*i + 1], k0.y, a1);
                a2 = ffma2(q2[2*i + 2], k1.x, a2);
                a3 = ffma2(q2[2*i + 3], k1.y, a3);
                a0 = ffma2(q2[2*i + 4], k2.x, a0);
                a1 = ffma2(q2[2*i + 5], k2.y, a1);
                a2 = ffma2(q2[2*i + 6], k3.x, a2);
                a3 = ffma2(q2[2*i + 7], k3.y, a3);
            }
            u64 s01 = fadd2(a0, a1);
            u64 s23 = fadd2(a2, a3);
            u64 s   = fadd2(s01, s23);
            float lo, hi;
            unpack2(s, lo, hi);
            float acc = lo + hi;
            if (acc > best) { best = acc; bi = jt + j; }  // first-max semantics
        }
    }

    // gather v row -> out[b, i, h*64 + d]
    const float4* vrow = (const float4*)(g_v + ((size_t)h*CC + bi)*DD);
    float4* orow = (float4*)(out_base + (size_t)t * (HH*DD) + h*DD);
    #pragma unroll
    for (int i = 0; i < 16; i++) orow[i] = vrow[i];

    // codebook index: layout (b, h, i) as float
    int b = t / NN, ii = t - b*NN;
    float* idx_out = out_base + (size_t)BB*NN*HH*DD;
    idx_out[((size_t)b*HH + h)*NN + ii] = (float)bi;

    atomicAdd(&g_hist[h*CC + bi], 1);
}

// ---------------------------------------------------------------------------
// Phase C: perplexity per head from histogram.
// ---------------------------------------------------------------------------
__global__ void perp_kernel(float* __restrict__ out_base) {
    int h = blockIdx.x;
    __shared__ float red[256];
    float s = 0.f;
    const float inv = 1.0f / (float)BN;
    for (int c = threadIdx.x; c < CC; c += 256) {
        float m = (float)g_hist[h*CC + c] * inv;
        s += m * logf(m + 1e-10f);
    }
    red[threadIdx.x] = s;
    __syncthreads();
    for (int o = 128; o > 0; o >>= 1) {
        if (threadIdx.x < o) red[threadIdx.x] += red[threadIdx.x + o];
        __syncthreads();
    }
    if (threadIdx.x == 0) {
        size_t perp_off = (size_t)BB*NN*HH*DD + (size_t)BB*HH*NN;
        out_base[perp_off + h] = expf(-red[0]);
    }
}

// ---------------------------------------------------------------------------
extern "C" void kernel_launch(void* const* d_in, const int* in_sizes, int n_in,
                              void* d_out, int out_size) {
    const float* x  = (const float*)d_in[0];   // (B, N, H*D)
    const float* cb = (const float*)d_in[1];   // (H, C, D)
    const float* wk = (const float*)d_in[2];   // (H, D, D)
    const float* wv = (const float*)d_in[3];   // (H, D, D)
    float* out = (float*)d_out;

    zero_hist_kernel<<<(HH*CC + 255)/256, 256>>>();

    dim3 gkv(HH, CC/16);
    kv_kernel<<<gkv, 256>>>(cb, wk, wv);

    dim3 gb(BN/TOK, HH);
    argmax_kernel<<<gb, TOK>>>(x, out);

    perp_kernel<<<HH, 256>>>(out);
}

// round 3
// speedup vs baseline: 1.0158x; 1.0158x over previous
#include <cuda_runtime.h>
#include <math.h>
#include <stdint.h>

#define BB 2
#define NN 4096
#define HH 16
#define DD 64
#define CC 1024
#define BN (BB*NN)            // 8192 tokens
#define TAU 0.015f
#define FIX_TOK 32

// Scratch (no cudaMalloc allowed).
__device__ __align__(16) float g_k  [HH*CC*DD];   // exact projected keys
__device__ __align__(16) float g_ktf[HH*CC*DD];   // tf32-rounded keys
__device__ __align__(16) float g_v  [HH*CC*DD];   // projected values
__device__ int g_hist[HH*CC];
__device__ int g_idx[HH*BN];                      // argmax per (h, token); bit16 = flagged
__device__ int g_flag_cnt[HH];
__device__ int g_flag_list[HH][BN];

__device__ __forceinline__ float tf32r(float f) {
    asm("cvt.rna.tf32.f32 %0, %1;" : "=f"(f) : "f"(f));
    return f;
}

__device__ __forceinline__ void mma_tf32(float c[4], const uint32_t a[4],
                                         uint32_t b0, uint32_t b1) {
    asm volatile(
        "mma.sync.aligned.m16n8k8.row.col.f32.tf32.tf32.f32 "
        "{%0,%1,%2,%3}, {%4,%5,%6,%7}, {%8,%9}, {%0,%1,%2,%3};"
        : "+f"(c[0]), "+f"(c[1]), "+f"(c[2]), "+f"(c[3])
        : "r"(a[0]), "r"(a[1]), "r"(a[2]), "r"(a[3]), "r"(b0), "r"(b1));
}

__device__ __forceinline__ void upd(float& b, float& s, int& bi, float v, int j) {
    if (v > b) { s = b; b = v; bi = j; }
    else       { s = fmaxf(s, v); }
}

// ---------------------------------------------------------------------------
// Phase A: k = cb @ wk (exact + tf32 copy), v = cb @ wv
// ---------------------------------------------------------------------------
__global__ void kv_kernel(const float* __restrict__ cb,
                          const float* __restrict__ wk,
                          const float* __restrict__ wv) {
    int h  = blockIdx.x;
    int c0 = blockIdx.y * 16;
    __shared__ float s_wk[DD*DD];
    __shared__ float s_wv[DD*DD];
    __shared__ float s_cb[16*DD];
    int tid = threadIdx.x;
    for (int i = tid; i < DD*DD; i += 256) {
        s_wk[i] = wk[h*DD*DD + i];
        s_wv[i] = wv[h*DD*DD + i];
    }
    for (int i = tid; i < 16*DD; i += 256)
        s_cb[i] = cb[(size_t)h*CC*DD + (size_t)c0*DD + i];
    __syncthreads();
    int d  = tid & 63;
    int cl = tid >> 6;
    for (int cc = cl; cc < 16; cc += 4) {
        float ak = 0.f, av = 0.f;
        #pragma unroll
        for (int e = 0; e < DD; e++) {
            float cbe = s_cb[cc*DD + e];
            ak = fmaf(cbe, s_wk[e*DD + d], ak);
            av = fmaf(cbe, s_wv[e*DD + d], av);
        }
        size_t off = ((size_t)h*CC + (c0 + cc))*DD + d;
        g_k[off]   = ak;
        g_ktf[off] = tf32r(ak);
        g_v[off]   = av;
    }
}

__global__ void zero_kernel() {
    int i = blockIdx.x * 256 + threadIdx.x;
    if (i < HH*CC) g_hist[i] = 0;
    if (i < HH)    g_flag_cnt[i] = 0;
}

// ---------------------------------------------------------------------------
// Phase B: TF32 mma logits + top-2 tracking.
// grid (BN/128, HH), block 128 (4 warps). Warp owns 32 tokens (2 M-tiles of
// m16n8k8). A fragments loaded once from gmem into regs; K chunks of 128 codes
// staged in smem (padded stride 68 floats -> conflict-free fragment LDS).
// ---------------------------------------------------------------------------
__global__ void __launch_bounds__(128)
mma_argmax_kernel(const float* __restrict__ x) {
    int h    = blockIdx.y;
    int tblk = blockIdx.x * 128;
    int tid  = threadIdx.x, warp = tid >> 5, lane = tid & 31;
    int g    = lane >> 2,   tg   = lane & 3;

    __shared__ float k_s[128 * 68];

    // A fragments: q scaled by 1/8, tf32-rounded. 2 M-tiles x 8 K-steps x 4.
    uint32_t a[2][8][4];
    {
        int r0 = tblk + warp*32 + g;
        const float* xb = x + (size_t)r0 * (HH*DD) + h*DD;
        #pragma unroll
        for (int m = 0; m < 2; m++) {
            #pragma unroll
            for (int ks = 0; ks < 8; ks++) {
                const float* p0 = xb + (size_t)(m*16    ) * (HH*DD) + ks*8 + tg;
                const float* p1 = xb + (size_t)(m*16 + 8) * (HH*DD) + ks*8 + tg;
                a[m][ks][0] = __float_as_uint(tf32r(p0[0] * 0.125f));
                a[m][ks][1] = __float_as_uint(tf32r(p1[0] * 0.125f));
                a[m][ks][2] = __float_as_uint(tf32r(p0[4] * 0.125f));
                a[m][ks][3] = __float_as_uint(tf32r(p1[4] * 0.125f));
            }
        }
    }

    float best[4], sec[4]; int bidx[4];
    #pragma unroll
    for (int s = 0; s < 4; s++) { best[s] = -INFINITY; sec[s] = -INFINITY; bidx[s] = 0; }

    for (int jt = 0; jt < CC; jt += 128) {
        __syncthreads();
        for (int i = tid; i < 128*16; i += 128) {
            int row = i >> 4, c4 = (i & 15) * 4;
            float4 v = *(const float4*)(g_ktf + ((size_t)h*CC + jt + row)*DD + c4);
            *(float4*)&k_s[row*68 + c4] = v;
        }
        __syncthreads();

        #pragma unroll 1
        for (int nt = 0; nt < 16; nt++) {
            float c0[4] = {0,0,0,0}, c1[4] = {0,0,0,0};
            const float* kb = &k_s[(nt*8 + g)*68];
            #pragma unroll
            for (int ks = 0; ks < 8; ks++) {
                uint32_t b0 = __float_as_uint(kb[ks*8 + tg]);
                uint32_t b1 = __float_as_uint(kb[ks*8 + tg + 4]);
                mma_tf32(c0, a[0][ks], b0, b1);
                mma_tf32(c1, a[1][ks], b0, b1);
            }
            int code0 = jt + nt*8 + 2*tg;
            upd(best[0], sec[0], bidx[0], c0[0], code0);
            upd(best[0], sec[0], bidx[0], c0[1], code0+1);
            upd(best[1], sec[1], bidx[1], c0[2], code0);
            upd(best[1], sec[1], bidx[1], c0[3], code0+1);
            upd(best[2], sec[2], bidx[2], c1[0], code0);
            upd(best[2], sec[2], bidx[2], c1[1], code0+1);
            upd(best[3], sec[3], bidx[3], c1[2], code0);
            upd(best[3], sec[3], bidx[3], c1[3], code0+1);
        }
    }

    // reduce across the 4 lanes of each quad (same rows, different cols)
    #pragma unroll
    for (int off = 1; off < 4; off <<= 1) {
        #pragma unroll
        for (int s = 0; s < 4; s++) {
            float ob = __shfl_xor_sync(0xffffffffu, best[s], off);
            float os = __shfl_xor_sync(0xffffffffu, sec[s],  off);
            int   oi = __shfl_xor_sync(0xffffffffu, bidx[s], off);
            float ns = fmaxf(fmaxf(sec[s], os), fminf(best[s], ob));
            bool take = (ob > best[s]) || (ob == best[s] && oi < bidx[s]);
            if (take) { best[s] = ob; bidx[s] = oi; }
            sec[s] = ns;
        }
    }

    if (tg == 0) {
        #pragma unroll
        for (int s = 0; s < 4; s++) {
            int m = s >> 1, r8 = (s & 1) * 8;
            int tok = tblk + warp*32 + m*16 + g + r8;
            int flag = (best[s] - sec[s] < TAU) ? 1 : 0;
            g_idx[h*BN + tok] = bidx[s] | (flag << 16);
            if (flag) {
                int pos = atomicAdd(&g_flag_cnt[h], 1);
                g_flag_list[h][pos] = tok;
            }
        }
    }
}

// ---------------------------------------------------------------------------
// Phase B2: exact fp32 rescue for flagged tokens (near-ties in tf32).
// grid (HH, BN/FIX_TOK) blocks, 256 threads. Block (h, slot) processes up to
// 32 flagged tokens; 8 threads per token split the 1024 codes; k staged
// exactly in smem. Most blocks exit immediately (cnt small).
// ---------------------------------------------------------------------------
__global__ void __launch_bounds__(256)
fixup_kernel(const float* __restrict__ x) {
    int h    = blockIdx.x;
    int base = blockIdx.y * FIX_TOK;
    int cnt  = g_flag_cnt[h];
    if (base >= cnt) return;

    int tid   = threadIdx.x;
    int tslot = tid >> 3, part = tid & 7;
    int ntok  = cnt - base; if (ntok > FIX_TOK) ntok = FIX_TOK;
    bool act  = (tslot < ntok);
    int tok   = g_flag_list[h][base + (act ? tslot : 0)];

    float q[64];
    {
        const float4* xr = (const float4*)(x + (size_t)tok*(HH*DD) + h*DD);
        #pragma unroll
        for (int i = 0; i < 16; i++) {
            float4 v = xr[i];
            q[4*i]   = v.x * 0.125f; q[4*i+1] = v.y * 0.125f;
            q[4*i+2] = v.z * 0.125f; q[4*i+3] = v.w * 0.125f;
        }
    }

    __shared__ float k_s[128 * 68];
    __shared__ float sbest[FIX_TOK * 8];
    __shared__ int   sidx [FIX_TOK * 8];

    float best = -INFINITY; int bi = 0;

    for (int jt = 0; jt < CC; jt += 128) {
        __syncthreads();
        for (int i = tid; i < 128*16; i += 256) {
            int row = i >> 4, c4 = (i & 15) * 4;
            float4 v = *(const float4*)(g_k + ((size_t)h*CC + jt + row)*DD + c4);
            *(float4*)&k_s[row*68 + c4] = v;
        }
        __syncthreads();
        for (int cc = 0; cc < 16; cc++) {
            int cl = part*16 + cc;
            const float* kr = &k_s[cl*68];
            float a0 = 0.f, a1 = 0.f, a2 = 0.f, a3 = 0.f;
            #pragma unroll
            for (int d = 0; d < 64; d += 4) {
                a0 = fmaf(q[d],   kr[d],   a0);
                a1 = fmaf(q[d+1], kr[d+1], a1);
                a2 = fmaf(q[d+2], kr[d+2], a2);
                a3 = fmaf(q[d+3], kr[d+3], a3);
            }
            float acc = (a0 + a1) + (a2 + a3);
            int code = jt + cl;
            if (acc > best) { best = acc; bi = code; }
        }
    }

    __syncthreads();
    sbest[tslot*8 + part] = best;
    sidx [tslot*8 + part] = bi;
    __syncthreads();
    if (act && part == 0) {
        float b = best; int xi = bi;
        #pragma unroll
        for (int p = 1; p < 8; p++) {
            float ob = sbest[tslot*8 + p]; int oi = sidx[tslot*8 + p];
            if (ob > b || (ob == b && oi < xi)) { b = ob; xi = oi; }
        }
        g_idx[h*BN + tok] = xi;   // clean (flag bit cleared)
    }
}

// ---------------------------------------------------------------------------
// Phase C: gather v rows, write indices, histogram. 8 threads per (t,h).
// ---------------------------------------------------------------------------
__global__ void __launch_bounds__(256)
gather_kernel(float* __restrict__ out_base) {
    int gid = blockIdx.x * 256 + threadIdx.x;    // 0 .. BN*HH*8
    int s = gid & 7;
    int h = (gid >> 3) & 15;
    int t = gid >> 7;
    int idx = g_idx[h*BN + t] & 1023;
    const float4* vr = (const float4*)(g_v + ((size_t)h*CC + idx)*DD + s*8);
    float4* orow = (float4*)(out_base + (size_t)t*(HH*DD) + h*DD + s*8);
    orow[0] = vr[0]; orow[1] = vr[1];
    if (s == 0) {
        int b  = t >> 12;        // t / NN
        int ii = t & (NN - 1);
        float* idx_out = out_base + (size_t)BN*HH*DD;
        idx_out[((size_t)b*HH + h)*NN + ii] = (float)idx;
        atomicAdd(&g_hist[h*CC + idx], 1);
    }
}

// ---------------------------------------------------------------------------
// Phase D: perplexity per head.
// ---------------------------------------------------------------------------
__global__ void perp_kernel(float* __restrict__ out_base) {
    int h = blockIdx.x;
    __shared__ float red[256];
    float s = 0.f;
    const float inv = 1.0f / (float)BN;
    for (int c = threadIdx.x; c < CC; c += 256) {
        float m = (float)g_hist[h*CC + c] * inv;
        s += m * logf(m + 1e-10f);
    }
    red[threadIdx.x] = s;
    __syncthreads();
    for (int o = 128; o > 0; o >>= 1) {
        if (threadIdx.x < o) red[threadIdx.x] += red[threadIdx.x + o];
        __syncthreads();
    }
    if (threadIdx.x == 0) {
        size_t perp_off = (size_t)BN*HH*DD + (size_t)BB*HH*NN;
        out_base[perp_off + h] = expf(-red[0]);
    }
}

// ---------------------------------------------------------------------------
extern "C" void kernel_launch(void* const* d_in, const int* in_sizes, int n_in,
                              void* d_out, int out_size) {
    const float* x  = (const float*)d_in[0];   // (B, N, H*D)
    const float* cb = (const float*)d_in[1];   // (H, C, D)
    const float* wk = (const float*)d_in[2];   // (H, D, D)
    const float* wv = (const float*)d_in[3];   // (H, D, D)
    float* out = (float*)d_out;

    zero_kernel<<<(HH*CC + 255)/256, 256>>>();

    dim3 gkv(HH, CC/16);
    kv_kernel<<<gkv, 256>>>(cb, wk, wv);

    dim3 gm(BN/128, HH);
    mma_argmax_kernel<<<gm, 128>>>(x);

    dim3 gf(HH, BN/FIX_TOK);
    fixup_kernel<<<gf, 256>>>(x);

    gather_kernel<<<(BN*HH*8)/256, 256>>>(out);

    perp_kernel<<<HH, 256>>>(out);
}

// round 4
// speedup vs baseline: 1.3763x; 1.3549x over previous
#include <cuda_runtime.h>
#include <math.h>
#include <stdint.h>

#define BB 2
#define NN 4096
#define HH 16
#define DD 64
#define CC 1024
#define BN (BB*NN)            // 8192 tokens
#define TAU 0.015f

// Scratch (no cudaMalloc allowed).
__device__ __align__(16) float g_k  [HH*CC*DD];   // exact projected keys
__device__ __align__(16) float g_ktf[HH*CC*DD];   // tf32-rounded keys
__device__ __align__(16) float g_v  [HH*CC*DD];   // projected values
__device__ int g_hist[HH*CC];
__device__ int g_idx[HH*BN];                      // final argmax per (h, token)
__device__ int g_cntA, g_cntB;
__device__ int g_listA_e[HH*BN];                  // h*BN + tok
__device__ int g_listA_c[HH*BN];                  // i1 | (i2<<10)
__device__ int g_listB_e[HH*BN];

__device__ __forceinline__ float tf32r(float f) {
    asm("cvt.rna.tf32.f32 %0, %1;" : "=f"(f) : "f"(f));
    return f;
}

__device__ __forceinline__ void mma_tf32(float c[4], const uint32_t a[4],
                                         uint32_t b0, uint32_t b1) {
    asm volatile(
        "mma.sync.aligned.m16n8k8.row.col.f32.tf32.tf32.f32 "
        "{%0,%1,%2,%3}, {%4,%5,%6,%7}, {%8,%9}, {%0,%1,%2,%3};"
        : "+f"(c[0]), "+f"(c[1]), "+f"(c[2]), "+f"(c[3])
        : "r"(a[0]), "r"(a[1]), "r"(a[2]), "r"(a[3]), "r"(b0), "r"(b1));
}

// insert (v, j) into a top-3 (scores b1>=b2>=b3, indices i1,i2).
__device__ __forceinline__ void ins(float v, int j, float& b1, float& b2,
                                    float& b3, int& i1, int& i2) {
    if (v > b1 || (v == b1 && j < i1)) {
        b3 = b2; b2 = b1; i2 = i1; b1 = v; i1 = j;
    } else if (v > b2 || (v == b2 && j < i2)) {
        b3 = b2; b2 = v; i2 = j;
    } else if (v > b3) {
        b3 = v;
    }
}

// ---------------------------------------------------------------------------
// Phase A: k = cb @ wk (exact + tf32 copy), v = cb @ wv
// ---------------------------------------------------------------------------
__global__ void kv_kernel(const float* __restrict__ cb,
                          const float* __restrict__ wk,
                          const float* __restrict__ wv) {
    int h  = blockIdx.x;
    int c0 = blockIdx.y * 16;
    __shared__ float s_wk[DD*DD];
    __shared__ float s_wv[DD*DD];
    __shared__ float s_cb[16*DD];
    int tid = threadIdx.x;
    for (int i = tid; i < DD*DD; i += 256) {
        s_wk[i] = wk[h*DD*DD + i];
        s_wv[i] = wv[h*DD*DD + i];
    }
    for (int i = tid; i < 16*DD; i += 256)
        s_cb[i] = cb[(size_t)h*CC*DD + (size_t)c0*DD + i];
    __syncthreads();
    int d  = tid & 63;
    int cl = tid >> 6;
    for (int cc = cl; cc < 16; cc += 4) {
        float ak = 0.f, av = 0.f;
        #pragma unroll
        for (int e = 0; e < DD; e++) {
            float cbe = s_cb[cc*DD + e];
            ak = fmaf(cbe, s_wk[e*DD + d], ak);
            av = fmaf(cbe, s_wv[e*DD + d], av);
        }
        size_t off = ((size_t)h*CC + (c0 + cc))*DD + d;
        g_k[off]   = ak;
        g_ktf[off] = tf32r(ak);
        g_v[off]   = av;
    }
}

__global__ void zero_kernel() {
    int i = blockIdx.x * 256 + threadIdx.x;
    if (i < HH*CC) g_hist[i] = 0;
    if (i == 0) { g_cntA = 0; g_cntB = 0; }
}

// ---------------------------------------------------------------------------
// Phase B: TF32 mma logits + top-3 tracking.
// grid (BN/128, HH), block 128 (4 warps). Warp owns 32 tokens (2 M-tiles).
// ---------------------------------------------------------------------------
__global__ void __launch_bounds__(128)
mma_argmax_kernel(const float* __restrict__ x) {
    int h    = blockIdx.y;
    int tblk = blockIdx.x * 128;
    int tid  = threadIdx.x, warp = tid >> 5, lane = tid & 31;
    int g    = lane >> 2,   tg   = lane & 3;

    __shared__ float k_s[128 * 68];

    // A fragments: q scaled by 1/8, tf32-rounded. 2 M-tiles x 8 K-steps x 4.
    uint32_t a[2][8][4];
    {
        int r0 = tblk + warp*32 + g;
        const float* xb = x + (size_t)r0 * (HH*DD) + h*DD;
        #pragma unroll
        for (int m = 0; m < 2; m++) {
            #pragma unroll
            for (int ks = 0; ks < 8; ks++) {
                const float* p0 = xb + (size_t)(m*16    ) * (HH*DD) + ks*8 + tg;
                const float* p1 = xb + (size_t)(m*16 + 8) * (HH*DD) + ks*8 + tg;
                a[m][ks][0] = __float_as_uint(tf32r(p0[0] * 0.125f));
                a[m][ks][1] = __float_as_uint(tf32r(p1[0] * 0.125f));
                a[m][ks][2] = __float_as_uint(tf32r(p0[4] * 0.125f));
                a[m][ks][3] = __float_as_uint(tf32r(p1[4] * 0.125f));
            }
        }
    }

    float b1[4], b2[4], b3[4]; int i1[4], i2[4];
    #pragma unroll
    for (int s = 0; s < 4; s++) {
        b1[s] = -INFINITY; b2[s] = -INFINITY; b3[s] = -INFINITY;
        i1[s] = 0; i2[s] = 0;
    }

    for (int jt = 0; jt < CC; jt += 128) {
        __syncthreads();
        for (int i = tid; i < 128*16; i += 128) {
            int row = i >> 4, c4 = (i & 15) * 4;
            float4 v = *(const float4*)(g_ktf + ((size_t)h*CC + jt + row)*DD + c4);
            *(float4*)&k_s[row*68 + c4] = v;
        }
        __syncthreads();

        #pragma unroll 1
        for (int nt = 0; nt < 16; nt++) {
            float c0[4] = {0,0,0,0}, c1[4] = {0,0,0,0};
            const float* kb = &k_s[(nt*8 + g)*68];
            #pragma unroll
            for (int ks = 0; ks < 8; ks++) {
                uint32_t v0 = __float_as_uint(kb[ks*8 + tg]);
                uint32_t v1 = __float_as_uint(kb[ks*8 + tg + 4]);
                mma_tf32(c0, a[0][ks], v0, v1);
                mma_tf32(c1, a[1][ks], v0, v1);
            }
            int code0 = jt + nt*8 + 2*tg;
            ins(c0[0], code0,   b1[0], b2[0], b3[0], i1[0], i2[0]);
            ins(c0[1], code0+1, b1[0], b2[0], b3[0], i1[0], i2[0]);
            ins(c0[2], code0,   b1[1], b2[1], b3[1], i1[1], i2[1]);
            ins(c0[3], code0+1, b1[1], b2[1], b3[1], i1[1], i2[1]);
            ins(c1[0], code0,   b1[2], b2[2], b3[2], i1[2], i2[2]);
            ins(c1[1], code0+1, b1[2], b2[2], b3[2], i1[2], i2[2]);
            ins(c1[2], code0,   b1[3], b2[3], b3[3], i1[3], i2[3]);
            ins(c1[3], code0+1, b1[3], b2[3], b3[3], i1[3], i2[3]);
        }
    }

    // reduce top-3 across the 4 lanes of each quad (same rows, diff cols)
    #pragma unroll
    for (int off = 1; off < 4; off <<= 1) {
        #pragma unroll
        for (int s = 0; s < 4; s++) {
            float ob1 = __shfl_xor_sync(0xffffffffu, b1[s], off);
            float ob2 = __shfl_xor_sync(0xffffffffu, b2[s], off);
            float ob3 = __shfl_xor_sync(0xffffffffu, b3[s], off);
            int   oi1 = __shfl_xor_sync(0xffffffffu, i1[s], off);
            int   oi2 = __shfl_xor_sync(0xffffffffu, i2[s], off);
            ins(ob1, oi1, b1[s], b2[s], b3[s], i1[s], i2[s]);
            ins(ob2, oi2, b1[s], b2[s], b3[s], i1[s], i2[s]);
            if (ob3 > b3[s]) b3[s] = ob3;   // ob3 can never outrank merged b2
        }
    }

    if (tg == 0) {
        #pragma unroll
        for (int s = 0; s < 4; s++) {
            int m = s >> 1, r8 = (s & 1) * 8;
            int tok = tblk + warp*32 + m*16 + g + r8;
            int e = h*BN + tok;
            g_idx[e] = i1[s];
            if (b1[s] - b3[s] < TAU) {
                int pos = atomicAdd(&g_cntB, 1);
                g_listB_e[pos] = e;
            } else if (b1[s] - b2[s] < TAU) {
                int pos = atomicAdd(&g_cntA, 1);
                g_listA_e[pos] = e;
                g_listA_c[pos] = i1[s] | (i2[s] << 10);
            }
        }
    }
}

// ---------------------------------------------------------------------------
// Phase B2a: level-A rescue — exact fp32 compare of the top-2 candidates.
// Grid-stride; one thread per flagged entry. Exact 4-way accumulation order
// (same as validated round-1 kernel).
// ---------------------------------------------------------------------------
__global__ void __launch_bounds__(256)
fixA_kernel(const float* __restrict__ x) {
    int cnt = g_cntA;
    for (int i = blockIdx.x * 256 + threadIdx.x; i < cnt; i += gridDim.x * 256) {
        int e   = g_listA_e[i];
        int c   = g_listA_c[i];
        int ia  = c & 1023, ib = (c >> 10) & 1023;
        int h   = e >> 13;            // e / BN
        int tok = e & (BN - 1);

        const float4* xq = (const float4*)(x + (size_t)tok*(HH*DD) + h*DD);
        const float4* ka = (const float4*)(g_k + ((size_t)h*CC + ia)*DD);
        const float4* kb = (const float4*)(g_k + ((size_t)h*CC + ib)*DD);

        float a0=0,a1=0,a2=0,a3=0, c0=0,c1=0,c2=0,c3=0;
        #pragma unroll
        for (int q4 = 0; q4 < 16; q4++) {
            float4 qv = xq[q4];
            qv.x *= 0.125f; qv.y *= 0.125f; qv.z *= 0.125f; qv.w *= 0.125f;
            float4 va = ka[q4];
            float4 vb = kb[q4];
            a0 = fmaf(qv.x, va.x, a0); a1 = fmaf(qv.y, va.y, a1);
            a2 = fmaf(qv.z, va.z, a2); a3 = fmaf(qv.w, va.w, a3);
            c0 = fmaf(qv.x, vb.x, c0); c1 = fmaf(qv.y, vb.y, c1);
            c2 = fmaf(qv.z, vb.z, c2); c3 = fmaf(qv.w, vb.w, c3);
        }
        float da = (a0 + a1) + (a2 + a3);
        float db = (c0 + c1) + (c2 + c3);
        int best = (db > da || (db == da && ib < ia)) ? ib : ia;
        g_idx[e] = best;
    }
}

// ---------------------------------------------------------------------------
// Phase B2b: level-B rescue — full exact argmax, one warp per entry (~0.2%).
// Lane l scans codes l, l+32, ...; q staged per-warp in smem (broadcast LDS).
// ---------------------------------------------------------------------------
__global__ void __launch_bounds__(256)
fixB_kernel(const float* __restrict__ x) {
    __shared__ float q_s[8][64];
    int warp = threadIdx.x >> 5, lane = threadIdx.x & 31;
    int gw   = blockIdx.x * 8 + warp;
    int cnt  = g_cntB;

    for (int i = gw; i < cnt; i += gridDim.x * 8) {
        int e   = g_listB_e[i];
        int h   = e >> 13;
        int tok = e & (BN - 1);

        // stage scaled q
        {
            const float* xq = x + (size_t)tok*(HH*DD) + h*DD;
            q_s[warp][lane]      = xq[lane]      * 0.125f;
            q_s[warp][lane + 32] = xq[lane + 32] * 0.125f;
        }
        __syncwarp();

        float best = -INFINITY; int bi = 0;
        for (int cc = lane; cc < CC; cc += 32) {
            const float4* kr = (const float4*)(g_k + ((size_t)h*CC + cc)*DD);
            float a0=0,a1=0,a2=0,a3=0;
            #pragma unroll
            for (int q4 = 0; q4 < 16; q4++) {
                float4 kv = __ldg(&kr[q4]);
                a0 = fmaf(q_s[warp][4*q4+0], kv.x, a0);
                a1 = fmaf(q_s[warp][4*q4+1], kv.y, a1);
                a2 = fmaf(q_s[warp][4*q4+2], kv.z, a2);
                a3 = fmaf(q_s[warp][4*q4+3], kv.w, a3);
            }
            float acc = (a0 + a1) + (a2 + a3);
            if (acc > best) { best = acc; bi = cc; }   // strictly increasing cc
        }
        // warp argmax reduce (first-max: smaller index wins ties)
        #pragma unroll
        for (int off = 16; off > 0; off >>= 1) {
            float ob = __shfl_down_sync(0xffffffffu, best, off);
            int   oi = __shfl_down_sync(0xffffffffu, bi,   off);
            if (ob > best || (ob == best && oi < bi)) { best = ob; bi = oi; }
        }
        if (lane == 0) g_idx[e] = bi;
        __syncwarp();
    }
}

// ---------------------------------------------------------------------------
// Phase C: gather v rows, write indices, histogram. 8 threads per (t,h).
// ---------------------------------------------------------------------------
__global__ void __launch_bounds__(256)
gather_kernel(float* __restrict__ out_base) {
    int gid = blockIdx.x * 256 + threadIdx.x;    // 0 .. BN*HH*8
    int s = gid & 7;
    int h = (gid >> 3) & 15;
    int t = gid >> 7;
    int idx = g_idx[h*BN + t] & 1023;
    const float4* vr = (const float4*)(g_v + ((size_t)h*CC + idx)*DD + s*8);
    float4* orow = (float4*)(out_base + (size_t)t*(HH*DD) + h*DD + s*8);
    orow[0] = vr[0]; orow[1] = vr[1];
    if (s == 0) {
        int b  = t >> 12;
        int ii = t & (NN - 1);
        float* idx_out = out_base + (size_t)BN*HH*DD;
        idx_out[((size_t)b*HH + h)*NN + ii] = (float)idx;
        atomicAdd(&g_hist[h*CC + idx], 1);
    }
}

// ---------------------------------------------------------------------------
// Phase D: perplexity per head.
// ---------------------------------------------------------------------------
__global__ void perp_kernel(float* __restrict__ out_base) {
    int h = blockIdx.x;
    __shared__ float red[256];
    float s = 0.f;
    const float inv = 1.0f / (float)BN;
    for (int c = threadIdx.x; c < CC; c += 256) {
        float m = (float)g_hist[h*CC + c] * inv;
        s += m * logf(m + 1e-10f);
    }
    red[threadIdx.x] = s;
    __syncthreads();
    for (int o = 128; o > 0; o >>= 1) {
        if (threadIdx.x < o) red[threadIdx.x] += red[threadIdx.x + o];
        __syncthreads();
    }
    if (threadIdx.x == 0) {
        size_t perp_off = (size_t)BN*HH*DD + (size_t)BB*HH*NN;
        out_base[perp_off + h] = expf(-red[0]);
    }
}

// ---------------------------------------------------------------------------
extern "C" void kernel_launch(void* const* d_in, const int* in_sizes, int n_in,
                              void* d_out, int out_size) {
    const float* x  = (const float*)d_in[0];   // (B, N, H*D)
    const float* cb = (const float*)d_in[1];   // (H, C, D)
    const float* wk = (const float*)d_in[2];   // (H, D, D)
    const float* wv = (const float*)d_in[3];   // (H, D, D)
    float* out = (float*)d_out;

    zero_kernel<<<(HH*CC + 255)/256, 256>>>();

    dim3 gkv(HH, CC/16);
    kv_kernel<<<gkv, 256>>>(cb, wk, wv);

    dim3 gm(BN/128, HH);
    mma_argmax_kernel<<<gm, 128>>>(x);

    fixA_kernel<<<64, 256>>>(x);
    fixB_kernel<<<32, 256>>>(x);

    gather_kernel<<<(BN*HH*8)/256, 256>>>(out);

    perp_kernel<<<HH, 256>>>(out);
}